// round 3
// baseline (speedup 1.0000x reference)
#include <cuda_runtime.h>
#include <math.h>

// bs=4096, nt=2048. Output depends only on the LAST batch row:
//   S    = sum_j [ (y-mu)^2/sigma + log(sigma) ]   over row (bs-1)
//   loss = 0.5 * (S + nt*log(2*pi)) / (nt*bs)
// 24 KiB total input -> single-block latency-floor reduction.
// R2: fast-math intrinsics (__fdividef, __logf) to collapse the IEEE
// div/log helper sequences that dominated the in-kernel critical path.

#define BS 4096
#define NT 2048
#define LOG_2PI 1.8378770664093453f

__global__ __launch_bounds__(512, 1)
void criterion_lastrow_kernel(const float* __restrict__ mu,
                              const float* __restrict__ sigma,
                              const float* __restrict__ target_y,
                              float* __restrict__ out) {
    const int tid = threadIdx.x;                      // 0..511
    const long long base = (long long)(BS - 1) * NT;  // start of last row

    // 512 threads * 4 floats = 2048 = NT. Fully coalesced float4 loads.
    const float4 m = reinterpret_cast<const float4*>(mu       + base)[tid];
    const float4 s = reinterpret_cast<const float4*>(sigma    + base)[tid];
    const float4 y = reinterpret_cast<const float4*>(target_y + base)[tid];

    const float d0 = y.x - m.x;
    const float d1 = y.y - m.y;
    const float d2 = y.z - m.z;
    const float d3 = y.w - m.w;

    // __fdividef: MUFU.RCP + FMUL; __logf: MUFU.LG2 + FMUL.
    // sigma >= 0.1 guaranteed, so fast paths are safe and accurate enough.
    float acc;
    acc  = __fdividef(d0 * d0, s.x) + __logf(s.x);
    acc += __fdividef(d1 * d1, s.y) + __logf(s.y);
    acc += __fdividef(d2 * d2, s.z) + __logf(s.z);
    acc += __fdividef(d3 * d3, s.w) + __logf(s.w);

    // Warp reduction
    #pragma unroll
    for (int off = 16; off > 0; off >>= 1)
        acc += __shfl_xor_sync(0xFFFFFFFFu, acc, off);

    __shared__ float warp_sums[16];
    const int wid = tid >> 5;
    const int lid = tid & 31;
    if (lid == 0) warp_sums[wid] = acc;
    __syncthreads();

    if (wid == 0) {
        float v = (lid < 16) ? warp_sums[lid] : 0.0f;
        #pragma unroll
        for (int off = 8; off > 0; off >>= 1)
            v += __shfl_xor_sync(0xFFFFFFFFu, v, off);
        if (lid == 0) {
            // 0.5 / (NT*BS), with the nt*log(2pi) offset folded in.
            const float scale = 0.5f / ((float)NT * (float)BS);
            out[0] = (v + (float)NT * LOG_2PI) * scale;
        }
    }
}

extern "C" void kernel_launch(void* const* d_in, const int* in_sizes, int n_in,
                              void* d_out, int out_size) {
    const float* mu       = (const float*)d_in[0];
    const float* sigma    = (const float*)d_in[1];
    const float* target_y = (const float*)d_in[2];
    criterion_lastrow_kernel<<<1, 512>>>(mu, sigma, target_y, (float*)d_out);
}